// round 1
// baseline (speedup 1.0000x reference)
#include <cuda_runtime.h>
#include <math.h>

// ---------------- problem constants ----------------
namespace {
constexpr int NB = 128;                       // batch
constexpr int C0 = 30, H0 = 15, W0 = 15;      // input
constexpr int C1 = 256, H1 = 13, W1 = 13, P1 = 169;  // after conv1
constexpr int C2 = 256, H2 = 11, W2 = 11, P2 = 121;  // after conv2
constexpr int NCAPS = 3872, IND = 8, OUTD = 16, NCLS = 16;
constexpr int NFLAT = C2 * P2;                // 30976
constexpr int NCHUNKS = 88, NPC = 44;         // 88*44 = 3872
constexpr int DEC1 = 328, DEC2 = 192, DEC3 = 6750;
}

// ---------------- scratch (static device memory, no allocs) ----------------
__device__ __align__(16) float g_h[NB * C1 * P1];          // conv1 out   (22.1 MB)
__device__ float g_bn_scale[C1];
__device__ float g_bn_shift[C1];
__device__ __align__(16) float g_pbuf[NB * NFLAT];         // conv2 out   (15.9 MB)
__device__ __align__(16) float g_caps[NCAPS * IND * NB];   // caps_t[n*8+j][b] (15.9 MB)
__device__ __align__(16) float g_wt[NCAPS * 2048];         // caps_w transposed [n][o][i][j] (31.7 MB)
__device__ __align__(16) float g_spart[(size_t)NCHUNKS * NB * 256]; // routing partial sums (11.5 MB)
__device__ float g_out_sum[NB * 256];                      // sum of outs over routing iters
__device__ float g_masked[NB * 256];
__device__ float g_r1[NB * DEC1];
__device__ float g_r2[NB * DEC2];

// ---------------- caps_w transpose: [o][n][i][j] -> [n][o][i][j] ----------------
__global__ void k_transpose_w(const float* __restrict__ cw) {
  int idx = blockIdx.x * 256 + threadIdx.x;       // over 16*3872*128
  if (idx >= NCLS * NCAPS * 128) return;
  int o = idx / (NCAPS * 128);
  int rem = idx - o * (NCAPS * 128);
  int n = rem >> 7;
  int ij = rem & 127;
  g_wt[n * 2048 + o * 128 + ij] = cw[idx];
}

// ---------------- conv1: 30->256, 3x3 valid, 15x15 -> 13x13 ----------------
__global__ void __launch_bounds__(256) k_conv1(const float* __restrict__ x,
                                               const float* __restrict__ w,
                                               const float* __restrict__ bias) {
  __shared__ float xs[C0 * H0 * W0];   // 6750 floats
  __shared__ float ws[16 * C0 * 9];    // 4320 floats
  const int b = blockIdx.y, cot = blockIdx.x;     // 16 co-tiles of 16
  const int tid = threadIdx.x;
  const float* xb = x + (size_t)b * (C0 * H0 * W0);
  for (int i = tid; i < C0 * H0 * W0; i += 256) xs[i] = xb[i];
  const float* wb = w + (size_t)cot * 16 * C0 * 9;
  for (int i = tid; i < 16 * C0 * 9; i += 256) ws[i] = wb[i];
  __syncthreads();
  const int p0 = tid & 63, cg = tid >> 6;         // 4 co-groups of 4 co
  int ph[3], pw[3];
  bool pv[3];
#pragma unroll
  for (int k = 0; k < 3; k++) {
    int p = p0 + 64 * k;
    pv[k] = p < P1;
    int pp = pv[k] ? p : 0;
    ph[k] = pp / W1; pw[k] = pp - (pp / W1) * W1;
  }
  float acc[4][3];
#pragma unroll
  for (int c = 0; c < 4; c++)
#pragma unroll
    for (int k = 0; k < 3; k++) acc[c][k] = 0.f;
  for (int ci = 0; ci < C0; ci++) {
    const float* xc = xs + ci * (H0 * W0);
#pragma unroll
    for (int kh = 0; kh < 3; kh++) {
#pragma unroll
      for (int kw = 0; kw < 3; kw++) {
        float wv[4];
#pragma unroll
        for (int c = 0; c < 4; c++)
          wv[c] = ws[(cg * 4 + c) * (C0 * 9) + ci * 9 + kh * 3 + kw];
#pragma unroll
        for (int k = 0; k < 3; k++) {
          float xv = xc[(ph[k] + kh) * W0 + pw[k] + kw];
#pragma unroll
          for (int c = 0; c < 4; c++) acc[c][k] += wv[c] * xv;
        }
      }
    }
  }
#pragma unroll
  for (int c = 0; c < 4; c++) {
    int co = cot * 16 + cg * 4 + c;
    float bs = bias[co];
#pragma unroll
    for (int k = 0; k < 3; k++)
      if (pv[k]) g_h[((size_t)b * C1 + co) * P1 + p0 + 64 * k] = acc[c][k] + bs;
  }
}

// ---------------- batchnorm stats (train-mode batch stats), folded ----------------
__global__ void k_bnstats(const float* __restrict__ gamma, const float* __restrict__ beta) {
  const int c = blockIdx.x, tid = threadIdx.x;
  float s = 0.f, s2 = 0.f;
  for (int i = tid; i < NB * P1; i += 256) {
    int b = i / P1, p = i - (i / P1) * P1;
    float v = g_h[((size_t)b * C1 + c) * P1 + p];
    s += v; s2 += v * v;
  }
  __shared__ float rs[256], rq[256];
  rs[tid] = s; rq[tid] = s2;
  __syncthreads();
  for (int st = 128; st > 0; st >>= 1) {
    if (tid < st) { rs[tid] += rs[tid + st]; rq[tid] += rq[tid + st]; }
    __syncthreads();
  }
  if (tid == 0) {
    const float inv_n = 1.f / (float)(NB * P1);
    float mean = rs[0] * inv_n;
    float var = fmaxf(rq[0] * inv_n - mean * mean, 0.f);
    float sc = gamma[c] * rsqrtf(var + 1e-5f);
    g_bn_scale[c] = sc;
    g_bn_shift[c] = beta[c] - mean * sc;
  }
}

// ---------------- conv2 (BN+relu fused on input): 256->256, 13x13 -> 11x11 ----------------
__global__ void __launch_bounds__(256) k_conv2(const float* __restrict__ w2,
                                               const float* __restrict__ b2) {
  __shared__ float xs[16 * P1];    // 2704 floats
  __shared__ float ws[64 * 144];   // 9216 floats
  const int b = blockIdx.y, cot = blockIdx.x;     // 4 co-tiles of 64
  const int tid = threadIdx.x;
  const int ps = tid & 31, cg = tid >> 5;         // 8 co-groups of 8, 4 positions stride 32
  int ph[4], pw[4];
  bool pv[4];
#pragma unroll
  for (int k = 0; k < 4; k++) {
    int p = ps + 32 * k;
    pv[k] = p < P2;
    int pp = pv[k] ? p : 0;
    ph[k] = pp / W2; pw[k] = pp - (pp / W2) * W2;
  }
  float acc[8][4];
#pragma unroll
  for (int c = 0; c < 8; c++)
#pragma unroll
    for (int k = 0; k < 4; k++) acc[c][k] = 0.f;
  for (int cc = 0; cc < 16; cc++) {               // 16 ci-chunks of 16
    __syncthreads();
    for (int i = tid; i < 16 * P1; i += 256) {
      int cl = i / P1, p = i - (i / P1) * P1;
      int c = cc * 16 + cl;
      float v = g_h[((size_t)b * C1 + c) * P1 + p];
      v = v * g_bn_scale[c] + g_bn_shift[c];
      xs[i] = v > 0.f ? v : 0.f;
    }
    for (int i = tid; i < 64 * 144; i += 256) {
      int col = i / 144, r = i - (i / 144) * 144;
      ws[i] = w2[((size_t)(cot * 64 + col)) * 2304 + cc * 144 + r];
    }
    __syncthreads();
    for (int cil = 0; cil < 16; cil++) {
      const float* xc = xs + cil * P1;
      const float* wc = ws + (cg * 8) * 144 + cil * 9;
#pragma unroll
      for (int kh = 0; kh < 3; kh++) {
#pragma unroll
        for (int kw = 0; kw < 3; kw++) {
          float wv[8];
#pragma unroll
          for (int c = 0; c < 8; c++) wv[c] = wc[c * 144 + kh * 3 + kw];
          float xv[4];
#pragma unroll
          for (int k = 0; k < 4; k++) xv[k] = xc[(ph[k] + kh) * W1 + pw[k] + kw];
#pragma unroll
          for (int c = 0; c < 8; c++)
#pragma unroll
            for (int k = 0; k < 4; k++) acc[c][k] += wv[c] * xv[k];
        }
      }
    }
  }
#pragma unroll
  for (int c = 0; c < 8; c++) {
    int co = cot * 64 + cg * 8 + c;
    float bs = b2[co];
#pragma unroll
    for (int k = 0; k < 4; k++)
      if (pv[k]) g_pbuf[(size_t)b * NFLAT + co * P2 + ps + 32 * k] = acc[c][k] + bs;
  }
}

// ---------------- primary capsule squash + transpose to [n*8+j][b] ----------------
__global__ void k_squash(void) {
  const int n = blockIdx.x, b = threadIdx.x;      // 128 threads = batch
  const float4* src = (const float4*)(g_pbuf + (size_t)b * NFLAT + n * IND);
  float4 a0 = src[0], a1 = src[1];
  float v[8] = {a0.x, a0.y, a0.z, a0.w, a1.x, a1.y, a1.z, a1.w};
  float ss = 0.f;
#pragma unroll
  for (int j = 0; j < 8; j++) ss += v[j] * v[j];
  float nrm = sqrtf(ss);
  float sc = ss / (1.f + ss) / (nrm + 1e-8f);
#pragma unroll
  for (int j = 0; j < 8; j++) g_caps[((size_t)n * IND + j) * NB + b] = v[j] * sc;
}

// ---------------- routing pass: recompute x_hat, softmax coupling, partial s ----------------
// block = 32 b x 4 i-quarters (warp = one i-quarter -> caps_w smem reads are warp broadcasts)
template <int PASS>
__global__ void __launch_bounds__(128) k_route() {
  __shared__ float ws[2048];           // caps_w[n] as [o][i][j]
  __shared__ float red[128 * 17];      // logit reduction, pitch 17 = conflict-free
  const int tid = threadIdx.x;
  const int iq = tid >> 5, bl = tid & 31;
  const int b = blockIdx.y * 32 + bl;
  float outa[16][4];
  if (PASS) {
#pragma unroll
    for (int o = 0; o < 16; o++)
#pragma unroll
      for (int ii = 0; ii < 4; ii++)
        outa[o][ii] = g_out_sum[b * 256 + o * 16 + iq * 4 + ii];
  }
  float s[16][4];
#pragma unroll
  for (int o = 0; o < 16; o++)
#pragma unroll
    for (int ii = 0; ii < 4; ii++) s[o][ii] = 0.f;
  const int n0 = blockIdx.x * NPC;
  for (int nn = 0; nn < NPC; nn++) {
    const int n = n0 + nn;
    __syncthreads();
    {
      float4* d = (float4*)ws;
      const float4* sr = (const float4*)(g_wt + (size_t)n * 2048);
#pragma unroll
      for (int i = 0; i < 4; i++) d[tid + i * 128] = sr[tid + i * 128];
    }
    __syncthreads();
    float cj[8];
#pragma unroll
    for (int j = 0; j < 8; j++) cj[j] = g_caps[((size_t)n * 8 + j) * NB + b];
    float c[16];
    if (PASS) {
      // logits: b_log[b,o,n] = out_sum[b,o,:] . x_hat[b,o,n,:]
#pragma unroll
      for (int o = 0; o < 16; o++) {
        const float* wo = ws + o * 128 + iq * 32;
        float lg = 0.f;
#pragma unroll
        for (int ii = 0; ii < 4; ii++) {
          float v = 0.f;
#pragma unroll
          for (int j = 0; j < 8; j++) v += wo[ii * 8 + j] * cj[j];
          lg += outa[o][ii] * v;
        }
        red[tid * 17 + o] = lg;
      }
      __syncthreads();
      float m = -3.4e38f;
#pragma unroll
      for (int o = 0; o < 16; o++) {
        c[o] = red[bl * 17 + o] + red[(32 + bl) * 17 + o] +
               red[(64 + bl) * 17 + o] + red[(96 + bl) * 17 + o];
        m = fmaxf(m, c[o]);
      }
      float den = 0.f;
#pragma unroll
      for (int o = 0; o < 16; o++) { c[o] = expf(c[o] - m); den += c[o]; }
      float inv = 1.f / den;
#pragma unroll
      for (int o = 0; o < 16; o++) c[o] *= inv;
    } else {
#pragma unroll
      for (int o = 0; o < 16; o++) c[o] = 0.0625f;   // softmax of zeros
    }
    // s[b,o,:] += c[b,o,n] * x_hat[b,o,n,:]  (recompute x_hat)
#pragma unroll
    for (int o = 0; o < 16; o++) {
      const float* wo = ws + o * 128 + iq * 32;
#pragma unroll
      for (int ii = 0; ii < 4; ii++) {
        float v = 0.f;
#pragma unroll
        for (int j = 0; j < 8; j++) v += wo[ii * 8 + j] * cj[j];
        s[o][ii] += c[o] * v;
      }
    }
  }
  float* dst = g_spart + ((size_t)blockIdx.x * NB + b) * 256 + iq * 4;
#pragma unroll
  for (int o = 0; o < 16; o++)
#pragma unroll
    for (int ii = 0; ii < 4; ii++) dst[o * 16 + ii] = s[o][ii];
}

// ---------------- reduce partials + squash (+ final: length & mask) ----------------
__global__ void k_reduce_squash(const float* __restrict__ y, float* __restrict__ d_out,
                                int first, int final_) {
  const int b = blockIdx.x, tid = threadIdx.x;    // 256 threads = (o,i)
  float v = 0.f;
  for (int ch = 0; ch < NCHUNKS; ch++)
    v += g_spart[((size_t)ch * NB + b) * 256 + tid];
  float ss = v * v;
#pragma unroll
  for (int m = 1; m < 16; m <<= 1) ss += __shfl_xor_sync(0xffffffffu, ss, m);
  float nrm = sqrtf(ss);
  float sc = ss / (1.f + ss) / (nrm + 1e-8f);
  float ov = v * sc;
  if (!final_) {
    if (first) g_out_sum[b * 256 + tid] = ov;
    else g_out_sum[b * 256 + tid] += ov;
  } else {
    int o = tid >> 4, i = tid & 15;
    if (i == 0) d_out[b * NCLS + o] = sc * nrm;    // ||squash(s)|| = scale * ||s||
    g_masked[b * 256 + tid] = ov * y[b * NCLS + o];
  }
}

// ---------------- decoder MLP ----------------
__global__ void k_dec1(const float* __restrict__ w1, const float* __restrict__ b1) {
  __shared__ float m[256];
  const int b = blockIdx.x, tid = threadIdx.x;    // 328 threads
  if (tid < 256) m[tid] = g_masked[b * 256 + tid];
  __syncthreads();
  float acc = b1[tid];
  for (int k = 0; k < 256; k++) acc += m[k] * w1[k * DEC1 + tid];
  g_r1[b * DEC1 + tid] = 1.f / (1.f + expf(-acc));
}

__global__ void k_dec2(const float* __restrict__ w2, const float* __restrict__ b2) {
  __shared__ float m[DEC1];
  const int b = blockIdx.x, tid = threadIdx.x;    // 192 threads
  for (int i = tid; i < DEC1; i += DEC2) m[i] = g_r1[b * DEC1 + i];
  __syncthreads();
  float acc = b2[tid];
  for (int k = 0; k < DEC1; k++) acc += m[k] * w2[k * DEC2 + tid];
  g_r2[b * DEC2 + tid] = 1.f / (1.f + expf(-acc));
}

__global__ void k_dec3(const float* __restrict__ w3, const float* __restrict__ b3,
                       float* __restrict__ d_out) {
  __shared__ float m[DEC2];
  const int b = blockIdx.x;
  const int j = blockIdx.y * 256 + threadIdx.x;
  if (threadIdx.x < DEC2) m[threadIdx.x] = g_r2[b * DEC2 + threadIdx.x];
  __syncthreads();
  if (j >= DEC3) return;
  float acc = b3[j];
  for (int k = 0; k < DEC2; k++) acc += m[k] * w3[(size_t)k * DEC3 + j];
  d_out[NB * NCLS + (size_t)b * DEC3 + j] = acc;
}

// ---------------- launcher ----------------
extern "C" void kernel_launch(void* const* d_in, const int* in_sizes, int n_in,
                              void* d_out, int out_size) {
  const float* x   = (const float*)d_in[0];
  const float* y   = (const float*)d_in[1];
  const float* c1w = (const float*)d_in[2];
  const float* c1b = (const float*)d_in[3];
  const float* bng = (const float*)d_in[4];
  const float* bnb = (const float*)d_in[5];
  const float* c2w = (const float*)d_in[6];
  const float* c2b = (const float*)d_in[7];
  const float* cpw = (const float*)d_in[8];
  const float* dw1 = (const float*)d_in[9];
  const float* db1 = (const float*)d_in[10];
  const float* dw2 = (const float*)d_in[11];
  const float* db2 = (const float*)d_in[12];
  const float* dw3 = (const float*)d_in[13];
  const float* db3 = (const float*)d_in[14];
  float* out = (float*)d_out;
  (void)in_sizes; (void)n_in; (void)out_size;

  k_transpose_w<<<(NCLS * NCAPS * 128 + 255) / 256, 256>>>(cpw);
  k_conv1<<<dim3(16, NB), 256>>>(x, c1w, c1b);
  k_bnstats<<<C1, 256>>>(bng, bnb);
  k_conv2<<<dim3(4, NB), 256>>>(c2w, c2b);
  k_squash<<<NCAPS, NB>>>();

  k_route<0><<<dim3(NCHUNKS, 4), 128>>>();
  k_reduce_squash<<<NB, 256>>>(y, out, 1, 0);
  k_route<1><<<dim3(NCHUNKS, 4), 128>>>();
  k_reduce_squash<<<NB, 256>>>(y, out, 0, 0);
  k_route<1><<<dim3(NCHUNKS, 4), 128>>>();
  k_reduce_squash<<<NB, 256>>>(y, out, 0, 1);

  k_dec1<<<NB, DEC1>>>(dw1, db1);
  k_dec2<<<NB, DEC2>>>(dw2, db2);
  k_dec3<<<dim3(NB, (DEC3 + 255) / 256), 256>>>(dw3, db3, out);
}

// round 4
// speedup vs baseline: 1.5077x; 1.5077x over previous
#include <cuda_runtime.h>
#include <math.h>

// ---------------- problem constants ----------------
namespace {
constexpr int NB = 128;                       // batch
constexpr int C0 = 30, H0 = 15, W0 = 15;      // input
constexpr int C1 = 256, W1 = 13, P1 = 169;    // after conv1 (13x13)
constexpr int C2 = 256, W2 = 11, P2 = 121;    // after conv2 (11x11)
constexpr int NCAPS = 3872, IND = 8, NCLS = 16;
constexpr int NFLAT = C2 * P2;                // 30976
constexpr int NCHUNKS = 88, NPC = 44;         // 88*44 = 3872
constexpr int DEC1 = 328, DEC2 = 192, DEC3 = 6750;
}

// ---------------- scratch (static device memory, no allocs) ----------------
__device__ __align__(16) float g_h[NB * C1 * P1];          // conv1 out
__device__ float g_bn_scale[C1];
__device__ float g_bn_shift[C1];
__device__ __align__(16) float g_pbuf[NB * NFLAT];         // conv2 out
__device__ __align__(16) float g_caps[NCAPS * IND * NB];   // caps_t[n*8+j][b]
__device__ __align__(16) float g_wt[NCAPS * 2048];         // caps_w [n][o][i][j]
__device__ __align__(16) float g_w1t[270 * 256];           // conv1 w [r][co]
__device__ __align__(16) float g_w2t[2304 * 256];          // conv2 w [r][co]
__device__ __align__(16) float g_spart[(size_t)NCHUNKS * NB * 256];
__device__ float g_out_sum[NB * 256];
__device__ float g_masked[NB * 256];
__device__ float g_r1[NB * DEC1];
__device__ float g_r2[NB * DEC2];

// ---------------- tiled transpose into fixed device globals ----------------
// which==0: c1w [256][270] -> g_w1t [270][256]
// which==1: c2w [256][2304] -> g_w2t [2304][256]
__global__ void k_tr(const float* __restrict__ src, int M, int N, int which) {
  float* __restrict__ dst = which ? g_w2t : g_w1t;
  __shared__ float t[32][33];
  const int tx = threadIdx.x;
  const int x = blockIdx.x * 32 + tx;
  const int y0 = blockIdx.y * 32;
  for (int j = threadIdx.y; j < 32; j += 8) {
    int y = y0 + j;
    if (x < N && y < M) t[j][tx] = src[(size_t)y * N + x];
  }
  __syncthreads();
  const int xo = y0 + tx;
  const int yo0 = blockIdx.x * 32;
  for (int j = threadIdx.y; j < 32; j += 8) {
    int yo = yo0 + j;
    if (xo < M && yo < N) dst[(size_t)yo * M + xo] = t[tx][j];
  }
}

// ---------------- caps_w transpose: [o][n][i][j] -> [n][o][i][j] ----------------
__global__ void k_transpose_w(const float* __restrict__ cw) {
  int idx = blockIdx.x * 256 + threadIdx.x;       // over 16*3872*128
  if (idx >= NCLS * NCAPS * 128) return;
  int o = idx / (NCAPS * 128);
  int rem = idx - o * (NCAPS * 128);
  int n = rem >> 7;
  int ij = rem & 127;
  g_wt[n * 2048 + o * 128 + ij] = cw[idx];
}

// ---------------- conv1: 30->256, 3x3 valid, 15x15 -> 13x13 ----------------
__global__ void __launch_bounds__(256) k_conv1(const float* __restrict__ x,
                                               const float* __restrict__ bias) {
  __shared__ __align__(16) float xs[C0 * H0 * W0];   // 6750
  __shared__ __align__(16) float ws[270 * 16];       // [r][co_local]
  const int b = blockIdx.y, cot = blockIdx.x;     // 16 co-tiles of 16
  const int tid = threadIdx.x;
  const float* xb = x + (size_t)b * (C0 * H0 * W0);
  for (int i = tid; i < C0 * H0 * W0; i += 256) xs[i] = xb[i];
  for (int i = tid; i < 270 * 16; i += 256) {
    int r = i >> 4, col = i & 15;
    ws[i] = g_w1t[r * 256 + cot * 16 + col];
  }
  __syncthreads();
  const int p0 = tid & 63, cg = tid >> 6;         // 4 co-groups of 4 co
  int ph[3], pw[3];
  bool pv[3];
#pragma unroll
  for (int k = 0; k < 3; k++) {
    int p = p0 + 64 * k;
    pv[k] = p < P1;
    int pp = pv[k] ? p : 0;
    ph[k] = pp / W1; pw[k] = pp - (pp / W1) * W1;
  }
  float acc[4][3];
#pragma unroll
  for (int c = 0; c < 4; c++)
#pragma unroll
    for (int k = 0; k < 3; k++) acc[c][k] = 0.f;
  for (int ci = 0; ci < C0; ci++) {
    const float* xc = xs + ci * (H0 * W0);
#pragma unroll
    for (int kh = 0; kh < 3; kh++) {
#pragma unroll
      for (int kw = 0; kw < 3; kw++) {
        float4 wv = *(const float4*)&ws[(ci * 9 + kh * 3 + kw) * 16 + cg * 4];
#pragma unroll
        for (int k = 0; k < 3; k++) {
          float xv = xc[(ph[k] + kh) * W0 + pw[k] + kw];
          acc[0][k] += wv.x * xv;
          acc[1][k] += wv.y * xv;
          acc[2][k] += wv.z * xv;
          acc[3][k] += wv.w * xv;
        }
      }
    }
  }
#pragma unroll
  for (int c = 0; c < 4; c++) {
    int co = cot * 16 + cg * 4 + c;
    float bs = bias[co];
#pragma unroll
    for (int k = 0; k < 3; k++)
      if (pv[k]) g_h[((size_t)b * C1 + co) * P1 + p0 + 64 * k] = acc[c][k] + bs;
  }
}

// ---------------- batchnorm stats (train-mode batch stats), folded ----------------
__global__ void k_bnstats(const float* __restrict__ gamma, const float* __restrict__ beta) {
  const int c = blockIdx.x, tid = threadIdx.x;
  float s = 0.f, s2 = 0.f;
  for (int i = tid; i < NB * P1; i += 256) {
    int b = i / P1, p = i - (i / P1) * P1;
    float v = g_h[((size_t)b * C1 + c) * P1 + p];
    s += v; s2 += v * v;
  }
  __shared__ float rs[256], rq[256];
  rs[tid] = s; rq[tid] = s2;
  __syncthreads();
  for (int st = 128; st > 0; st >>= 1) {
    if (tid < st) { rs[tid] += rs[tid + st]; rq[tid] += rq[tid + st]; }
    __syncthreads();
  }
  if (tid == 0) {
    const float inv_n = 1.f / (float)(NB * P1);
    float mean = rs[0] * inv_n;
    float var = fmaxf(rq[0] * inv_n - mean * mean, 0.f);
    float sc = gamma[c] * rsqrtf(var + 1e-5f);
    g_bn_scale[c] = sc;
    g_bn_shift[c] = beta[c] - mean * sc;
  }
}

// ---------------- conv2 (BN+relu fused on input): 256->256, 13x13 -> 11x11 ----------------
// block = 128 co x 128 pos; thread tile 8co x 8pos; ci chunks of 8
__global__ void __launch_bounds__(256, 2) k_conv2(const float* __restrict__ b2) {
  __shared__ __align__(16) float xs[8 * P1];     // 1352
  __shared__ __align__(16) float ws[72 * 128];   // 9216: [r][co_local]
  const int b = blockIdx.y, cot = blockIdx.x;     // 2 co-tiles of 128
  const int tid = threadIdx.x;
  const int pg = tid & 15, cg = tid >> 4;         // 16 pos groups, 16 co groups of 8
  int ph[8], pw[8];
  bool pv[8];
#pragma unroll
  for (int k = 0; k < 8; k++) {
    int p = pg + 16 * k;
    pv[k] = p < P2;
    int pp = pv[k] ? p : 0;
    ph[k] = pp / W2; pw[k] = pp - (pp / W2) * W2;
  }
  float acc[8][8];
#pragma unroll
  for (int c = 0; c < 8; c++)
#pragma unroll
    for (int k = 0; k < 8; k++) acc[c][k] = 0.f;
  for (int cc = 0; cc < 32; cc++) {               // 32 ci-chunks of 8
    __syncthreads();
    for (int i = tid; i < 8 * P1; i += 256) {
      int cl = i / P1, p = i - (i / P1) * P1;
      int c = cc * 8 + cl;
      float v = g_h[((size_t)b * C1 + c) * P1 + p];
      v = v * g_bn_scale[c] + g_bn_shift[c];
      xs[i] = v > 0.f ? v : 0.f;
    }
    for (int i = tid; i < 72 * 128; i += 256) {
      int r = i >> 7, col = i & 127;
      ws[i] = g_w2t[(size_t)(cc * 72 + r) * 256 + cot * 128 + col];
    }
    __syncthreads();
#pragma unroll
    for (int cil = 0; cil < 8; cil++) {
      const float* xc = xs + cil * P1;
#pragma unroll
      for (int kh = 0; kh < 3; kh++) {
#pragma unroll
        for (int kw = 0; kw < 3; kw++) {
          const float* wr = ws + (cil * 9 + kh * 3 + kw) * 128 + cg * 8;
          float4 wa = *(const float4*)wr;
          float4 wb = *(const float4*)(wr + 4);
          float xv[8];
#pragma unroll
          for (int k = 0; k < 8; k++) xv[k] = xc[(ph[k] + kh) * W1 + pw[k] + kw];
#pragma unroll
          for (int k = 0; k < 8; k++) {
            acc[0][k] += wa.x * xv[k];
            acc[1][k] += wa.y * xv[k];
            acc[2][k] += wa.z * xv[k];
            acc[3][k] += wa.w * xv[k];
            acc[4][k] += wb.x * xv[k];
            acc[5][k] += wb.y * xv[k];
            acc[6][k] += wb.z * xv[k];
            acc[7][k] += wb.w * xv[k];
          }
        }
      }
    }
  }
#pragma unroll
  for (int c = 0; c < 8; c++) {
    int co = cot * 128 + cg * 8 + c;
    float bs = b2[co];
#pragma unroll
    for (int k = 0; k < 8; k++)
      if (pv[k]) g_pbuf[(size_t)b * NFLAT + co * P2 + pg + 16 * k] = acc[c][k] + bs;
  }
}

// ---------------- primary capsule squash + transpose to [n*8+j][b] ----------------
__global__ void k_squash(void) {
  const int n = blockIdx.x, b = threadIdx.x;
  const float4* src = (const float4*)(g_pbuf + (size_t)b * NFLAT + n * IND);
  float4 a0 = src[0], a1 = src[1];
  float v[8] = {a0.x, a0.y, a0.z, a0.w, a1.x, a1.y, a1.z, a1.w};
  float ss = 0.f;
#pragma unroll
  for (int j = 0; j < 8; j++) ss += v[j] * v[j];
  float nrm = sqrtf(ss);
  float sc = ss / (1.f + ss) / (nrm + 1e-8f);
#pragma unroll
  for (int j = 0; j < 8; j++) g_caps[((size_t)n * IND + j) * NB + b] = v[j] * sc;
}

// ---------------- routing pass: recompute x_hat, softmax coupling, partial s ----------------
// block = 32 b x 4 i-quarters; double-buffered weight staging; float4 smem reads
template <int PASS>
__global__ void __launch_bounds__(128) k_route() {
  __shared__ __align__(16) float ws[2 * 2048];
  __shared__ __align__(16) float red[128 * 17];
  const int tid = threadIdx.x;
  const int iq = tid >> 5, bl = tid & 31;
  const int b = blockIdx.y * 32 + bl;
  float outa[64];
  if (PASS) {
#pragma unroll
    for (int t = 0; t < 64; t++)
      outa[t] = g_out_sum[b * 256 + (t >> 2) * 16 + iq * 4 + (t & 3)];
  }
  float s[64];
#pragma unroll
  for (int t = 0; t < 64; t++) s[t] = 0.f;
  const int n0 = blockIdx.x * NPC;
  float4 pre[4];
  {
    const float4* sr = (const float4*)(g_wt + (size_t)n0 * 2048);
#pragma unroll
    for (int i = 0; i < 4; i++) pre[i] = sr[tid + i * 128];
  }
  int cur = 0;
  for (int nn = 0; nn < NPC; nn++) {
    const int n = n0 + nn;
    float4* wbuf = (float4*)(ws + cur * 2048);
#pragma unroll
    for (int i = 0; i < 4; i++) wbuf[tid + i * 128] = pre[i];
    __syncthreads();
    if (nn + 1 < NPC) {
      const float4* sr = (const float4*)(g_wt + (size_t)(n + 1) * 2048);
#pragma unroll
      for (int i = 0; i < 4; i++) pre[i] = sr[tid + i * 128];
    }
    float cj[8];
#pragma unroll
    for (int j = 0; j < 8; j++) cj[j] = g_caps[((size_t)n * 8 + j) * NB + b];
    const float* wb = ws + cur * 2048 + iq * 32;
    float c[16];
    if (PASS) {
#pragma unroll
      for (int o = 0; o < 16; o++) {
        const float4* w4 = (const float4*)(wb + o * 128);
        float lg = 0.f;
#pragma unroll
        for (int ii = 0; ii < 4; ii++) {
          float4 a = w4[2 * ii], d = w4[2 * ii + 1];
          float v = a.x * cj[0] + a.y * cj[1] + a.z * cj[2] + a.w * cj[3]
                  + d.x * cj[4] + d.y * cj[5] + d.z * cj[6] + d.w * cj[7];
          lg += outa[o * 4 + ii] * v;
        }
        red[tid * 17 + o] = lg;
      }
      __syncthreads();
      float m = -3.4e38f;
#pragma unroll
      for (int o = 0; o < 16; o++) {
        c[o] = red[bl * 17 + o] + red[(32 + bl) * 17 + o] +
               red[(64 + bl) * 17 + o] + red[(96 + bl) * 17 + o];
        m = fmaxf(m, c[o]);
      }
      float den = 0.f;
#pragma unroll
      for (int o = 0; o < 16; o++) { c[o] = expf(c[o] - m); den += c[o]; }
      float inv = 1.f / den;
#pragma unroll
      for (int o = 0; o < 16; o++) c[o] *= inv;
    }
#pragma unroll
    for (int o = 0; o < 16; o++) {
      const float4* w4 = (const float4*)(wb + o * 128);
      float co_ = PASS ? c[o] : 1.f;
#pragma unroll
      for (int ii = 0; ii < 4; ii++) {
        float4 a = w4[2 * ii], d = w4[2 * ii + 1];
        float v = a.x * cj[0] + a.y * cj[1] + a.z * cj[2] + a.w * cj[3]
                + d.x * cj[4] + d.y * cj[5] + d.z * cj[6] + d.w * cj[7];
        s[o * 4 + ii] += co_ * v;
      }
    }
    cur ^= 1;
  }
  const float fin = PASS ? 1.f : 0.0625f;   // pass0: softmax(0) = 1/16, applied once
  float* dst = g_spart + ((size_t)blockIdx.x * NB + b) * 256 + iq * 4;
#pragma unroll
  for (int o = 0; o < 16; o++)
#pragma unroll
    for (int ii = 0; ii < 4; ii++) dst[o * 16 + ii] = s[o * 4 + ii] * fin;
}

// ---------------- reduce partials + squash (+ final: length & mask) ----------------
__global__ void k_reduce_squash(const float* __restrict__ y, float* __restrict__ d_out,
                                int first, int final_) {
  const int b = blockIdx.x, tid = threadIdx.x;    // 256 threads = (o,i)
  float v = 0.f;
  for (int ch = 0; ch < NCHUNKS; ch++)
    v += g_spart[((size_t)ch * NB + b) * 256 + tid];
  float ss = v * v;
#pragma unroll
  for (int m = 1; m < 16; m <<= 1) ss += __shfl_xor_sync(0xffffffffu, ss, m);
  float nrm = sqrtf(ss);
  float sc = ss / (1.f + ss) / (nrm + 1e-8f);
  float ov = v * sc;
  if (!final_) {
    if (first) g_out_sum[b * 256 + tid] = ov;
    else g_out_sum[b * 256 + tid] += ov;
  } else {
    int o = tid >> 4, i = tid & 15;
    if (i == 0) d_out[b * NCLS + o] = sc * nrm;
    g_masked[b * 256 + tid] = ov * y[b * NCLS + o];
  }
}

// ---------------- decoder MLP ----------------
__global__ void k_dec1(const float* __restrict__ w1, const float* __restrict__ b1) {
  __shared__ float m[256];
  const int b = blockIdx.x, tid = threadIdx.x;    // 328 threads
  if (tid < 256) m[tid] = g_masked[b * 256 + tid];
  __syncthreads();
  float acc = b1[tid];
  for (int k = 0; k < 256; k++) acc += m[k] * w1[k * DEC1 + tid];
  g_r1[b * DEC1 + tid] = 1.f / (1.f + expf(-acc));
}

__global__ void k_dec2(const float* __restrict__ w2, const float* __restrict__ b2) {
  __shared__ float m[DEC1];
  const int b = blockIdx.x, tid = threadIdx.x;    // 192 threads
  for (int i = tid; i < DEC1; i += DEC2) m[i] = g_r1[b * DEC1 + i];
  __syncthreads();
  float acc = b2[tid];
  for (int k = 0; k < DEC1; k++) acc += m[k] * w2[k * DEC2 + tid];
  g_r2[b * DEC2 + tid] = 1.f / (1.f + expf(-acc));
}

// 4 batch rows per block: each w3 element reused 4x
__global__ void k_dec3(const float* __restrict__ w3, const float* __restrict__ b3,
                       float* __restrict__ d_out) {
  __shared__ float m[4 * DEC2];
  const int bq = blockIdx.y * 4;
  const int tid = threadIdx.x;
  const int j = blockIdx.x * 256 + tid;
  for (int i = tid; i < 4 * DEC2; i += 256)
    m[i] = g_r2[(bq + i / DEC2) * DEC2 + (i % DEC2)];
  __syncthreads();
  if (j >= DEC3) return;
  float acc[4];
  float bv = b3[j];
#pragma unroll
  for (int q = 0; q < 4; q++) acc[q] = bv;
  for (int k = 0; k < DEC2; k++) {
    float w = w3[(size_t)k * DEC3 + j];
#pragma unroll
    for (int q = 0; q < 4; q++) acc[q] += m[q * DEC2 + k] * w;
  }
#pragma unroll
  for (int q = 0; q < 4; q++)
    d_out[NB * NCLS + (size_t)(bq + q) * DEC3 + j] = acc[q];
}

// ---------------- launcher ----------------
extern "C" void kernel_launch(void* const* d_in, const int* in_sizes, int n_in,
                              void* d_out, int out_size) {
  const float* x   = (const float*)d_in[0];
  const float* y   = (const float*)d_in[1];
  const float* c1w = (const float*)d_in[2];
  const float* c1b = (const float*)d_in[3];
  const float* bng = (const float*)d_in[4];
  const float* bnb = (const float*)d_in[5];
  const float* c2w = (const float*)d_in[6];
  const float* c2b = (const float*)d_in[7];
  const float* cpw = (const float*)d_in[8];
  const float* dw1 = (const float*)d_in[9];
  const float* db1 = (const float*)d_in[10];
  const float* dw2 = (const float*)d_in[11];
  const float* db2 = (const float*)d_in[12];
  const float* dw3 = (const float*)d_in[13];
  const float* db3 = (const float*)d_in[14];
  float* out = (float*)d_out;
  (void)in_sizes; (void)n_in; (void)out_size;

  k_tr<<<dim3(9, 8), dim3(32, 8)>>>(c1w, 256, 270, 0);
  k_tr<<<dim3(72, 8), dim3(32, 8)>>>(c2w, 256, 2304, 1);
  k_transpose_w<<<(NCLS * NCAPS * 128 + 255) / 256, 256>>>(cpw);

  k_conv1<<<dim3(16, NB), 256>>>(x, c1b);
  k_bnstats<<<C1, 256>>>(bng, bnb);
  k_conv2<<<dim3(2, NB), 256>>>(c2b);
  k_squash<<<NCAPS, NB>>>();

  k_route<0><<<dim3(NCHUNKS, 4), 128>>>();
  k_reduce_squash<<<NB, 256>>>(y, out, 1, 0);
  k_route<1><<<dim3(NCHUNKS, 4), 128>>>();
  k_reduce_squash<<<NB, 256>>>(y, out, 0, 0);
  k_route<1><<<dim3(NCHUNKS, 4), 128>>>();
  k_reduce_squash<<<NB, 256>>>(y, out, 0, 1);

  k_dec1<<<NB, DEC1>>>(dw1, db1);
  k_dec2<<<NB, DEC2>>>(dw2, db2);
  k_dec3<<<dim3(27, 32), 256>>>(dw3, db3, out);
}

// round 7
// speedup vs baseline: 1.5806x; 1.0484x over previous
#include <cuda_runtime.h>
#include <math.h>

// ---------------- problem constants ----------------
namespace {
constexpr int NB = 128;                       // batch
constexpr int C0 = 30, H0 = 15, W0 = 15;      // input
constexpr int C1 = 256, W1 = 13, P1 = 169;    // after conv1 (13x13)
constexpr int C2 = 256, W2 = 11, P2 = 121;    // after conv2 (11x11)
constexpr int NCAPS = 3872, IND = 8, NCLS = 16;
constexpr int NFLAT = C2 * P2;                // 30976
constexpr int NCHUNKS = 88, NPC = 44;         // 88*44 = 3872
constexpr int DEC1 = 328, DEC2 = 192, DEC3 = 6750;
}

// ---------------- scratch (static device memory, no allocs) ----------------
__device__ __align__(16) float g_h[NB * C1 * P1];          // conv1 out
__device__ float g_bn_scale[C1];
__device__ float g_bn_shift[C1];
__device__ __align__(16) float g_pbuf[NB * NFLAT];         // conv2 out
__device__ __align__(16) float g_caps[NCAPS * IND * NB];   // caps_t[n*8+j][b]
__device__ __align__(16) float g_wt[NCAPS * 2048];         // caps_w [n][o][i][j]
__device__ __align__(16) float g_w1t[270 * 256];           // conv1 w [r][co]
__device__ __align__(16) float g_w2t[2304 * 256];          // conv2 w [r][co]
__device__ __align__(16) float g_spart[(size_t)NCHUNKS * NB * 256];
__device__ float g_out_sum[NB * 256];
__device__ float g_masked[NB * 256];
__device__ float g_r1[NB * DEC1];
__device__ float g_r2[NB * DEC2];

// ---------------- tiled transpose into fixed device globals ----------------
__global__ void k_tr(const float* __restrict__ src, int M, int N, int which) {
  float* __restrict__ dst = which ? g_w2t : g_w1t;
  __shared__ float t[32][33];
  const int tx = threadIdx.x;
  const int x = blockIdx.x * 32 + tx;
  const int y0 = blockIdx.y * 32;
  for (int j = threadIdx.y; j < 32; j += 8) {
    int y = y0 + j;
    if (x < N && y < M) t[j][tx] = src[(size_t)y * N + x];
  }
  __syncthreads();
  const int xo = y0 + tx;
  const int yo0 = blockIdx.x * 32;
  for (int j = threadIdx.y; j < 32; j += 8) {
    int yo = yo0 + j;
    if (xo < M && yo < N) dst[(size_t)yo * M + xo] = t[tx][j];
  }
}

// ---------------- caps_w transpose: [o][n][i][j] -> [n][o][i][j] ----------------
__global__ void k_transpose_w(const float* __restrict__ cw) {
  int idx = blockIdx.x * 256 + threadIdx.x;       // over 16*3872*128
  if (idx >= NCLS * NCAPS * 128) return;
  int o = idx / (NCAPS * 128);
  int rem = idx - o * (NCAPS * 128);
  int n = rem >> 7;
  int ij = rem & 127;
  g_wt[n * 2048 + o * 128 + ij] = cw[idx];
}

// ---------------- conv1: 30->256, 3x3 valid, 15x15 -> 13x13 ----------------
// co-tile 32/block; thread tile 8co x 3pos; weights staged in 2 ci-halves (smem fit)
__global__ void __launch_bounds__(256) k_conv1(const float* __restrict__ x,
                                               const float* __restrict__ bias) {
  __shared__ __align__(16) float xs[C0 * H0 * W0];   // 27000 B
  __shared__ __align__(16) float ws[135 * 32];       // 17280 B: [r][co_local]
  const int b = blockIdx.y, cot = blockIdx.x;     // 8 co-tiles of 32
  const int tid = threadIdx.x;
  const float* xb = x + (size_t)b * (C0 * H0 * W0);
  for (int i = tid; i < C0 * H0 * W0; i += 256) xs[i] = xb[i];
  const int p0 = tid & 63, cg = tid >> 6;         // 4 co-groups of 8 co
  int ph[3], pw[3];
  bool pv[3];
#pragma unroll
  for (int k = 0; k < 3; k++) {
    int p = p0 + 64 * k;
    pv[k] = p < P1;
    int pp = pv[k] ? p : 0;
    ph[k] = pp / W1; pw[k] = pp - (pp / W1) * W1;
  }
  float acc[8][3];
#pragma unroll
  for (int c = 0; c < 8; c++)
#pragma unroll
    for (int k = 0; k < 3; k++) acc[c][k] = 0.f;
  for (int half = 0; half < 2; half++) {          // ci chunks of 15
    __syncthreads();
    for (int i = tid; i < 135 * 32; i += 256) {
      int r = i >> 5, col = i & 31;
      ws[i] = g_w1t[(half * 135 + r) * 256 + cot * 32 + col];
    }
    __syncthreads();
    for (int cil = 0; cil < 15; cil++) {
      const float* xc = xs + (half * 15 + cil) * (H0 * W0);
#pragma unroll
      for (int kh = 0; kh < 3; kh++) {
#pragma unroll
        for (int kw = 0; kw < 3; kw++) {
          const float* wr = ws + (cil * 9 + kh * 3 + kw) * 32 + cg * 8;
          float4 wa = *(const float4*)wr;
          float4 wb = *(const float4*)(wr + 4);
#pragma unroll
          for (int k = 0; k < 3; k++) {
            float xv = xc[(ph[k] + kh) * W0 + pw[k] + kw];
            acc[0][k] += wa.x * xv;
            acc[1][k] += wa.y * xv;
            acc[2][k] += wa.z * xv;
            acc[3][k] += wa.w * xv;
            acc[4][k] += wb.x * xv;
            acc[5][k] += wb.y * xv;
            acc[6][k] += wb.z * xv;
            acc[7][k] += wb.w * xv;
          }
        }
      }
    }
  }
#pragma unroll
  for (int c = 0; c < 8; c++) {
    int co = cot * 32 + cg * 8 + c;
    float bs = bias[co];
#pragma unroll
    for (int k = 0; k < 3; k++)
      if (pv[k]) g_h[((size_t)b * C1 + co) * P1 + p0 + 64 * k] = acc[c][k] + bs;
  }
}

// ---------------- batchnorm stats (train-mode batch stats), folded ----------------
__global__ void k_bnstats(const float* __restrict__ gamma, const float* __restrict__ beta) {
  const int c = blockIdx.x, tid = threadIdx.x;
  float s = 0.f, s2 = 0.f;
  for (int i = tid; i < NB * P1; i += 256) {
    int b = i / P1, p = i - (i / P1) * P1;
    float v = g_h[((size_t)b * C1 + c) * P1 + p];
    s += v; s2 += v * v;
  }
  __shared__ float rs[256], rq[256];
  rs[tid] = s; rq[tid] = s2;
  __syncthreads();
  for (int st = 128; st > 0; st >>= 1) {
    if (tid < st) { rs[tid] += rs[tid + st]; rq[tid] += rq[tid + st]; }
    __syncthreads();
  }
  if (tid == 0) {
    const float inv_n = 1.f / (float)(NB * P1);
    float mean = rs[0] * inv_n;
    float var = fmaxf(rq[0] * inv_n - mean * mean, 0.f);
    float sc = gamma[c] * rsqrtf(var + 1e-5f);
    g_bn_scale[c] = sc;
    g_bn_shift[c] = beta[c] - mean * sc;
  }
}

// ---------------- conv2 (BN+relu fused on input): 256->256, 13x13 -> 11x11 ----------------
__global__ void __launch_bounds__(256, 2) k_conv2(const float* __restrict__ b2) {
  __shared__ __align__(16) float xs[8 * P1];     // 1352
  __shared__ __align__(16) float ws[72 * 128];   // 9216: [r][co_local]
  const int b = blockIdx.y, cot = blockIdx.x;     // 2 co-tiles of 128
  const int tid = threadIdx.x;
  const int pg = tid & 15, cg = tid >> 4;         // 16 pos groups, 16 co groups of 8
  int ph[8], pw[8];
  bool pv[8];
#pragma unroll
  for (int k = 0; k < 8; k++) {
    int p = pg + 16 * k;
    pv[k] = p < P2;
    int pp = pv[k] ? p : 0;
    ph[k] = pp / W2; pw[k] = pp - (pp / W2) * W2;
  }
  float acc[8][8];
#pragma unroll
  for (int c = 0; c < 8; c++)
#pragma unroll
    for (int k = 0; k < 8; k++) acc[c][k] = 0.f;
  for (int cc = 0; cc < 32; cc++) {               // 32 ci-chunks of 8
    __syncthreads();
    for (int i = tid; i < 8 * P1; i += 256) {
      int cl = i / P1, p = i - (i / P1) * P1;
      int c = cc * 8 + cl;
      float v = g_h[((size_t)b * C1 + c) * P1 + p];
      v = v * g_bn_scale[c] + g_bn_shift[c];
      xs[i] = v > 0.f ? v : 0.f;
    }
    for (int i = tid; i < 72 * 128; i += 256) {
      int r = i >> 7, col = i & 127;
      ws[i] = g_w2t[(size_t)(cc * 72 + r) * 256 + cot * 128 + col];
    }
    __syncthreads();
#pragma unroll
    for (int cil = 0; cil < 8; cil++) {
      const float* xc = xs + cil * P1;
#pragma unroll
      for (int kh = 0; kh < 3; kh++) {
#pragma unroll
        for (int kw = 0; kw < 3; kw++) {
          const float* wr = ws + (cil * 9 + kh * 3 + kw) * 128 + cg * 8;
          float4 wa = *(const float4*)wr;
          float4 wb = *(const float4*)(wr + 4);
          float xv[8];
#pragma unroll
          for (int k = 0; k < 8; k++) xv[k] = xc[(ph[k] + kh) * W1 + pw[k] + kw];
#pragma unroll
          for (int k = 0; k < 8; k++) {
            acc[0][k] += wa.x * xv[k];
            acc[1][k] += wa.y * xv[k];
            acc[2][k] += wa.z * xv[k];
            acc[3][k] += wa.w * xv[k];
            acc[4][k] += wb.x * xv[k];
            acc[5][k] += wb.y * xv[k];
            acc[6][k] += wb.z * xv[k];
            acc[7][k] += wb.w * xv[k];
          }
        }
      }
    }
  }
#pragma unroll
  for (int c = 0; c < 8; c++) {
    int co = cot * 128 + cg * 8 + c;
    float bs = b2[co];
#pragma unroll
    for (int k = 0; k < 8; k++)
      if (pv[k]) g_pbuf[(size_t)b * NFLAT + co * P2 + pg + 16 * k] = acc[c][k] + bs;
  }
}

// ---------------- primary capsule squash + transpose to [n*8+j][b] ----------------
__global__ void k_squash(void) {
  const int n = blockIdx.x, b = threadIdx.x;
  const float4* src = (const float4*)(g_pbuf + (size_t)b * NFLAT + n * IND);
  float4 a0 = src[0], a1 = src[1];
  float v[8] = {a0.x, a0.y, a0.z, a0.w, a1.x, a1.y, a1.z, a1.w};
  float ss = 0.f;
#pragma unroll
  for (int j = 0; j < 8; j++) ss += v[j] * v[j];
  float nrm = sqrtf(ss);
  float sc = ss / (1.f + ss) / (nrm + 1e-8f);
#pragma unroll
  for (int j = 0; j < 8; j++) g_caps[((size_t)n * IND + j) * NB + b] = v[j] * sc;
}

// ---------------- routing pass ----------------
// 256 threads: bl = b-lane (32), iq = i-quarter (4), oh = o-half (2).
// Each thread: 8 o x 4 i. x_hat kept in registers between logit and s loops.
template <int PASS>
__global__ void __launch_bounds__(256) k_route() {
  __shared__ __align__(16) float ws[2 * 2048];
  __shared__ float red[256 * 9];       // logits, pitch 9 = conflict-free
  const int tid = threadIdx.x;
  const int bl = tid & 31;
  const int iq = (tid >> 5) & 3;
  const int oh = tid >> 7;
  const int b = blockIdx.y * 32 + bl;
  float outa[32];
  if (PASS) {
#pragma unroll
    for (int o8 = 0; o8 < 8; o8++)
#pragma unroll
      for (int ii = 0; ii < 4; ii++)
        outa[o8 * 4 + ii] = g_out_sum[b * 256 + (oh * 8 + o8) * 16 + iq * 4 + ii];
  }
  float s[32];
#pragma unroll
  for (int t = 0; t < 32; t++) s[t] = 0.f;
  const int n0 = blockIdx.x * NPC;
  float4 pre0, pre1;
  {
    const float4* sr = (const float4*)(g_wt + (size_t)n0 * 2048);
    pre0 = sr[tid]; pre1 = sr[tid + 256];
  }
  int cur = 0;
  for (int nn = 0; nn < NPC; nn++) {
    const int n = n0 + nn;
    float4* wbuf = (float4*)(ws + cur * 2048);
    wbuf[tid] = pre0; wbuf[tid + 256] = pre1;
    __syncthreads();
    if (nn + 1 < NPC) {
      const float4* sr = (const float4*)(g_wt + (size_t)(n + 1) * 2048);
      pre0 = sr[tid]; pre1 = sr[tid + 256];
    }
    float cj[8];
#pragma unroll
    for (int j = 0; j < 8; j++) cj[j] = g_caps[((size_t)n * 8 + j) * NB + b];
    const float* wb = ws + cur * 2048 + oh * 1024 + iq * 32;
    float v[32];
#pragma unroll
    for (int o8 = 0; o8 < 8; o8++) {
      const float4* w4 = (const float4*)(wb + o8 * 128);
#pragma unroll
      for (int ii = 0; ii < 4; ii++) {
        float4 a = w4[2 * ii], d = w4[2 * ii + 1];
        v[o8 * 4 + ii] = a.x * cj[0] + a.y * cj[1] + a.z * cj[2] + a.w * cj[3]
                       + d.x * cj[4] + d.y * cj[5] + d.z * cj[6] + d.w * cj[7];
      }
    }
    float c[8];
    if (PASS) {
#pragma unroll
      for (int o8 = 0; o8 < 8; o8++) {
        float lg = outa[o8 * 4] * v[o8 * 4] + outa[o8 * 4 + 1] * v[o8 * 4 + 1]
                 + outa[o8 * 4 + 2] * v[o8 * 4 + 2] + outa[o8 * 4 + 3] * v[o8 * 4 + 3];
        red[tid * 9 + o8] = lg;
      }
      __syncthreads();
      float lg16[16];
      float m = -3.4e38f;
#pragma unroll
      for (int o = 0; o < 16; o++) {
        int hh = o >> 3, o8 = o & 7;
        float t = red[((hh * 4 + 0) * 32 + bl) * 9 + o8]
                + red[((hh * 4 + 1) * 32 + bl) * 9 + o8]
                + red[((hh * 4 + 2) * 32 + bl) * 9 + o8]
                + red[((hh * 4 + 3) * 32 + bl) * 9 + o8];
        lg16[o] = t;
        m = fmaxf(m, t);
      }
      float den = 0.f;
#pragma unroll
      for (int o = 0; o < 16; o++) { lg16[o] = __expf(lg16[o] - m); den += lg16[o]; }
      float inv = 1.f / den;
#pragma unroll
      for (int o8 = 0; o8 < 8; o8++) c[o8] = lg16[oh * 8 + o8] * inv;
    }
#pragma unroll
    for (int o8 = 0; o8 < 8; o8++) {
      float co_ = PASS ? c[o8] : 1.f;
#pragma unroll
      for (int ii = 0; ii < 4; ii++) s[o8 * 4 + ii] += co_ * v[o8 * 4 + ii];
    }
    cur ^= 1;
  }
  const float fin = PASS ? 1.f : 0.0625f;   // pass0: softmax(0) = 1/16, applied once
  float* dst = g_spart + ((size_t)blockIdx.x * NB + b) * 256;
#pragma unroll
  for (int o8 = 0; o8 < 8; o8++)
#pragma unroll
    for (int ii = 0; ii < 4; ii++)
      dst[(oh * 8 + o8) * 16 + iq * 4 + ii] = s[o8 * 4 + ii] * fin;
}

// ---------------- reduce partials + squash (+ final: length & mask) ----------------
__global__ void k_reduce_squash(const float* __restrict__ y, float* __restrict__ d_out,
                                int first, int final_) {
  const int b = blockIdx.x, tid = threadIdx.x;    // 256 threads = (o,i)
  float v = 0.f;
  for (int ch = 0; ch < NCHUNKS; ch++)
    v += g_spart[((size_t)ch * NB + b) * 256 + tid];
  float ss = v * v;
#pragma unroll
  for (int m = 1; m < 16; m <<= 1) ss += __shfl_xor_sync(0xffffffffu, ss, m);
  float nrm = sqrtf(ss);
  float sc = ss / (1.f + ss) / (nrm + 1e-8f);
  float ov = v * sc;
  if (!final_) {
    if (first) g_out_sum[b * 256 + tid] = ov;
    else g_out_sum[b * 256 + tid] += ov;
  } else {
    int o = tid >> 4, i = tid & 15;
    if (i == 0) d_out[b * NCLS + o] = sc * nrm;
    g_masked[b * 256 + tid] = ov * y[b * NCLS + o];
  }
}

// ---------------- decoder MLP ----------------
__global__ void k_dec1(const float* __restrict__ w1, const float* __restrict__ b1) {
  __shared__ float m[256];
  const int b = blockIdx.x, tid = threadIdx.x;    // 328 threads
  if (tid < 256) m[tid] = g_masked[b * 256 + tid];
  __syncthreads();
  float acc = b1[tid];
  for (int k = 0; k < 256; k++) acc += m[k] * w1[k * DEC1 + tid];
  g_r1[b * DEC1 + tid] = 1.f / (1.f + __expf(-acc));
}

__global__ void k_dec2(const float* __restrict__ w2, const float* __restrict__ b2) {
  __shared__ float m[DEC1];
  const int b = blockIdx.x, tid = threadIdx.x;    // 192 threads
  for (int i = tid; i < DEC1; i += DEC2) m[i] = g_r1[b * DEC1 + i];
  __syncthreads();
  float acc = b2[tid];
  for (int k = 0; k < DEC1; k++) acc += m[k] * w2[k * DEC2 + tid];
  g_r2[b * DEC2 + tid] = 1.f / (1.f + __expf(-acc));
}

// 4 batch rows per block: each w3 read reused 4x
__global__ void k_dec3(const float* __restrict__ w3, const float* __restrict__ b3,
                       float* __restrict__ d_out) {
  __shared__ float m[4 * DEC2];
  const int bq = blockIdx.y * 4;
  const int tid = threadIdx.x;
  const int j = blockIdx.x * 256 + tid;
  for (int i = tid; i < 4 * DEC2; i += 256)
    m[i] = g_r2[(bq + i / DEC2) * DEC2 + (i % DEC2)];
  __syncthreads();
  if (j >= DEC3) return;
  float acc[4];
  float bv = b3[j];
#pragma unroll
  for (int q = 0; q < 4; q++) acc[q] = bv;
  for (int k = 0; k < DEC2; k++) {
    float w = w3[(size_t)k * DEC3 + j];
#pragma unroll
    for (int q = 0; q < 4; q++) acc[q] += m[q * DEC2 + k] * w;
  }
#pragma unroll
  for (int q = 0; q < 4; q++)
    d_out[NB * NCLS + (size_t)(bq + q) * DEC3 + j] = acc[q];
}

// ---------------- launcher ----------------
extern "C" void kernel_launch(void* const* d_in, const int* in_sizes, int n_in,
                              void* d_out, int out_size) {
  const float* x   = (const float*)d_in[0];
  const float* y   = (const float*)d_in[1];
  const float* c1w = (const float*)d_in[2];
  const float* c1b = (const float*)d_in[3];
  const float* bng = (const float*)d_in[4];
  const float* bnb = (const float*)d_in[5];
  const float* c2w = (const float*)d_in[6];
  const float* c2b = (const float*)d_in[7];
  const float* cpw = (const float*)d_in[8];
  const float* dw1 = (const float*)d_in[9];
  const float* db1 = (const float*)d_in[10];
  const float* dw2 = (const float*)d_in[11];
  const float* db2 = (const float*)d_in[12];
  const float* dw3 = (const float*)d_in[13];
  const float* db3 = (const float*)d_in[14];
  float* out = (float*)d_out;
  (void)in_sizes; (void)n_in; (void)out_size;

  k_tr<<<dim3(9, 8), dim3(32, 8)>>>(c1w, 256, 270, 0);
  k_tr<<<dim3(72, 8), dim3(32, 8)>>>(c2w, 256, 2304, 1);
  k_transpose_w<<<(NCLS * NCAPS * 128 + 255) / 256, 256>>>(cpw);

  k_conv1<<<dim3(8, NB), 256>>>(x, c1b);
  k_bnstats<<<C1, 256>>>(bng, bnb);
  k_conv2<<<dim3(2, NB), 256>>>(c2b);
  k_squash<<<NCAPS, NB>>>();

  k_route<0><<<dim3(NCHUNKS, 4), 256>>>();
  k_reduce_squash<<<NB, 256>>>(y, out, 1, 0);
  k_route<1><<<dim3(NCHUNKS, 4), 256>>>();
  k_reduce_squash<<<NB, 256>>>(y, out, 0, 0);
  k_route<1><<<dim3(NCHUNKS, 4), 256>>>();
  k_reduce_squash<<<NB, 256>>>(y, out, 0, 1);

  k_dec1<<<NB, DEC1>>>(dw1, db1);
  k_dec2<<<NB, DEC2>>>(dw2, db2);
  k_dec3<<<dim3(27, 32), 256>>>(dw3, db3, out);
}